// round 2
// baseline (speedup 1.0000x reference)
#include <cuda_runtime.h>
#include <cuda_bf16.h>

// CenterLossLayer: B=16384, C=1024, D=512, alpha=0.5
//   result[b]   = sum_d (features[b,d] - centers[labels[b],d])^2
//   delta[c,d]  = sum_{b: labels[b]==c} (centers[c,d] - features[b,d])
//   new_centers = centers - alpha * delta / (count_c + 1)
// d_out layout: [0 .. B) -> result (f32) ; [B .. B + C*D) -> new_centers (f32)

#define BATCH       16384
#define NUM_CLASSES 1024
#define FEAT_DIM    512
#define ALPHA       0.5f

#define G        4            // classes per block
#define THREADS  512
#define NWARPS   (THREADS / 32)
#define CAP      4096         // smem match-list capacity (expected ~64/block)

__global__ __launch_bounds__(THREADS)
void center_loss_fused_kernel(const float* __restrict__ features,
                              const float* __restrict__ centers,
                              const int*   __restrict__ labels,
                              float*       __restrict__ out_result,
                              float*       __restrict__ out_centers) {
    // smem: centers 8KB + delta 8KB + list 16KB + misc  (~33KB)
    __shared__ __align__(16) float s_centers[G][FEAT_DIM];
    __shared__ __align__(16) float s_delta[G][FEAT_DIM];
    __shared__ int s_count[G];
    __shared__ int s_list[CAP];
    __shared__ int s_n;

    const int t  = threadIdx.x;
    const int c0 = blockIdx.x * G;     // first class of this block's group

    // ---- init ----
    if (t < G)  s_count[t] = 0;
    if (t == 0) s_n = 0;
    #pragma unroll
    for (int g = 0; g < G; g++) {
        s_centers[g][t] = centers[(size_t)(c0 + g) * FEAT_DIM + t];  // THREADS == FEAT_DIM
        s_delta[g][t]   = 0.0f;
    }
    __syncthreads();

    // ---- scan labels, build match list ----
    const int4* lab4 = reinterpret_cast<const int4*>(labels);
    #pragma unroll
    for (int i = 0; i < BATCH / 4 / THREADS; i++) {       // 8 iterations
        int idx4 = i * THREADS + t;                       // coalesced
        int4 L   = lab4[idx4];
        int  b0  = idx4 * 4;
        int  ls[4] = {L.x, L.y, L.z, L.w};
        #pragma unroll
        for (int j = 0; j < 4; j++) {
            int g = ls[j] - c0;
            if ((unsigned)g < (unsigned)G) {
                int pos = atomicAdd(&s_n, 1);
                if (pos < CAP) s_list[pos] = (b0 + j) | (g << 14);  // b fits in 14 bits
                atomicAdd(&s_count[g], 1);
            }
        }
    }
    __syncthreads();
    const int n_match = min(s_n, CAP);

    // ---- warp-per-sample processing (no block barriers in this loop) ----
    const int warp = t >> 5;
    const int lane = t & 31;

    for (int i = warp; i < n_match; i += NWARPS) {
        int e = s_list[i];
        int b = e & 0x3FFF;
        int g = e >> 14;

        const float4* frow = reinterpret_cast<const float4*>(features + (size_t)b * FEAT_DIM);
        const float4* crow = reinterpret_cast<const float4*>(s_centers[g]);
        float*        drow = s_delta[g];

        float acc = 0.0f;
        #pragma unroll
        for (int k = 0; k < 4; k++) {
            int q = lane + 32 * k;          // float4 index within row (coalesced)
            float4 f = frow[q];
            float4 c = crow[q];
            float dx = c.x - f.x;
            float dy = c.y - f.y;
            float dz = c.z - f.z;
            float dw = c.w - f.w;
            acc += dx * dx + dy * dy + dz * dz + dw * dw;
            atomicAdd(drow + 4 * q + 0, dx);
            atomicAdd(drow + 4 * q + 1, dy);
            atomicAdd(drow + 4 * q + 2, dz);
            atomicAdd(drow + 4 * q + 3, dw);
        }

        // warp reduce sum of squares
        #pragma unroll
        for (int off = 16; off > 0; off >>= 1)
            acc += __shfl_down_sync(0xFFFFFFFFu, acc, off);
        if (lane == 0) out_result[b] = acc;
    }
    __syncthreads();

    // ---- finalize: new_centers = centers - alpha * delta / (count + 1) ----
    #pragma unroll
    for (int g = 0; g < G; g++) {
        float s = ALPHA / (float)(s_count[g] + 1);
        out_centers[(size_t)(c0 + g) * FEAT_DIM + t] = s_centers[g][t] - s * s_delta[g][t];
    }
}

// ---------------------------------------------------------------------------
extern "C" void kernel_launch(void* const* d_in, const int* in_sizes, int n_in,
                              void* d_out, int out_size) {
    const float* features = (const float*)d_in[0];
    const float* centers  = (const float*)d_in[1];
    const int*   labels   = (const int*)d_in[2];

    float* out_result      = (float*)d_out;          // [BATCH]
    float* out_new_centers = (float*)d_out + BATCH;  // [NUM_CLASSES * FEAT_DIM]

    center_loss_fused_kernel<<<NUM_CLASSES / G, THREADS>>>(
        features, centers, labels, out_result, out_new_centers);
}

// round 4
// speedup vs baseline: 1.8174x; 1.8174x over previous
#include <cuda_runtime.h>
#include <cuda_bf16.h>

// CenterLossLayer: B=16384, C=1024, D=512, alpha=0.5
//   result[b]   = sum_d (features[b,d] - centers[labels[b],d])^2
//   delta[c,d]  = sum_{b: labels[b]==c} (centers[c,d] - features[b,d])
//   new_centers = centers - alpha * delta / (count_c + 1)
// d_out: [0..B) result f32 ; [B .. B+C*D) new_centers f32

#define BATCH       16384
#define NUM_CLASSES 1024
#define FEAT_DIM    512
#define ALPHA       0.5f

#define G        2                 // classes per block
#define THREADS  256
#define NWARPS   (THREADS / 32)
#define NREP     (NWARPS / G)      // 4 replica accumulators per class
#define CAPG     1024              // per-class list capacity (expected ~16)
#define NF4      (FEAT_DIM / 4)    // 128 float4 per row

#define F4_ZERO make_float4(0.f, 0.f, 0.f, 0.f)

__device__ __forceinline__ float4 f4_sub(float4 a, float4 b) {
    return make_float4(a.x - b.x, a.y - b.y, a.z - b.z, a.w - b.w);
}
__device__ __forceinline__ void f4_acc(float4& a, float4 b) {
    a.x += b.x; a.y += b.y; a.z += b.z; a.w += b.w;
}
__device__ __forceinline__ float f4_dot(float4 a) {
    return a.x * a.x + a.y * a.y + a.z * a.z + a.w * a.w;
}

__global__ __launch_bounds__(THREADS, 3)
void center_loss_fused_kernel(const float* __restrict__ features,
                              const float* __restrict__ centers,
                              const int*   __restrict__ labels,
                              float*       __restrict__ out_result,
                              float*       __restrict__ out_centers) {
    __shared__ __align__(16) float s_centers[G * FEAT_DIM];          // 4 KB
    __shared__ __align__(16) float s_delta[G * NREP * FEAT_DIM];     // 16 KB
    __shared__ int s_list[G][CAPG];                                  // 8 KB
    __shared__ int s_gcnt[G];

    const int t  = threadIdx.x;
    const int c0 = blockIdx.x * G;

    if (t < G) s_gcnt[t] = 0;
    // load G center rows: G*NF4 = 256 float4s == THREADS
    reinterpret_cast<float4*>(s_centers)[t] =
        reinterpret_cast<const float4*>(centers + (size_t)c0 * FEAT_DIM)[t];
    __syncthreads();

    // ---- scan labels, build per-class match lists ----
    const int4* lab4 = reinterpret_cast<const int4*>(labels);
    #pragma unroll
    for (int i = 0; i < BATCH / 4 / THREADS; i++) {        // 16 iterations
        int idx4 = i * THREADS + t;                        // coalesced
        int4 L = lab4[idx4];
        int b0 = idx4 * 4;
        int ls[4] = {L.x, L.y, L.z, L.w};
        #pragma unroll
        for (int j = 0; j < 4; j++) {
            int g = ls[j] - c0;
            if ((unsigned)g < (unsigned)G) {
                int pos = atomicAdd(&s_gcnt[g], 1);
                if (pos < CAPG) s_list[g][pos] = b0 + j;
            }
        }
    }
    __syncthreads();

    // ---- warp-per-class, register accumulation, pipelined loads ----
    const int warp = t >> 5;
    const int lane = t & 31;
    const int g    = warp & (G - 1);
    const int r    = warp >> 1;                // replica id, 0..NREP-1
    const int cnt  = min(s_gcnt[g], CAPG);

    // center row cached in registers (lane's 16 floats)
    const float4* cen4 = reinterpret_cast<const float4*>(s_centers + g * FEAT_DIM);
    float4 c0v = cen4[lane +  0];
    float4 c1v = cen4[lane + 32];
    float4 c2v = cen4[lane + 64];
    float4 c3v = cen4[lane + 96];

    float4 a0 = F4_ZERO, a1 = F4_ZERO, a2 = F4_ZERO, a3 = F4_ZERO;

    int   i     = r;
    int   b_cur = (i < cnt) ? s_list[g][i] : -1;
    float4 f0, f1, f2, f3;
    if (b_cur >= 0) {
        const float4* fr = reinterpret_cast<const float4*>(features + (size_t)b_cur * FEAT_DIM);
        f0 = fr[lane]; f1 = fr[lane + 32]; f2 = fr[lane + 64]; f3 = fr[lane + 96];
    }

    while (b_cur >= 0) {
        // prefetch next sample (overlaps with current compute)
        int in = i + NREP;
        int b_next = (in < cnt) ? s_list[g][in] : -1;
        float4 n0, n1, n2, n3;
        if (b_next >= 0) {
            const float4* fr = reinterpret_cast<const float4*>(features + (size_t)b_next * FEAT_DIM);
            n0 = fr[lane]; n1 = fr[lane + 32]; n2 = fr[lane + 64]; n3 = fr[lane + 96];
        }

        // process current
        float4 d0 = f4_sub(c0v, f0);
        float4 d1 = f4_sub(c1v, f1);
        float4 d2 = f4_sub(c2v, f2);
        float4 d3 = f4_sub(c3v, f3);
        f4_acc(a0, d0); f4_acc(a1, d1); f4_acc(a2, d2); f4_acc(a3, d3);
        float sq = f4_dot(d0) + f4_dot(d1) + f4_dot(d2) + f4_dot(d3);

        #pragma unroll
        for (int off = 16; off > 0; off >>= 1)
            sq += __shfl_down_sync(0xFFFFFFFFu, sq, off);
        if (lane == 0) out_result[b_cur] = sq;

        f0 = n0; f1 = n1; f2 = n2; f3 = n3;
        b_cur = b_next; i = in;
    }

    // write replica accumulator (plain STS, full coverage — no init needed)
    float4* dd = reinterpret_cast<float4*>(s_delta + (size_t)(g * NREP + r) * FEAT_DIM);
    dd[lane] = a0; dd[lane + 32] = a1; dd[lane + 64] = a2; dd[lane + 96] = a3;
    __syncthreads();

    // ---- finalize: reduce replicas, new_centers = centers - alpha*delta/(count+1) ----
    {
        int gg = t / NF4;                  // t / 128 -> class within group
        int q  = t % NF4;
        float s = ALPHA / (float)(s_gcnt[gg] + 1);

        const float4* base = reinterpret_cast<const float4*>(s_delta);
        float4 acc = base[(gg * NREP + 0) * NF4 + q];
        f4_acc(acc, base[(gg * NREP + 1) * NF4 + q]);
        f4_acc(acc, base[(gg * NREP + 2) * NF4 + q]);
        f4_acc(acc, base[(gg * NREP + 3) * NF4 + q]);

        float4 ce = reinterpret_cast<const float4*>(s_centers)[gg * NF4 + q];
        float4 o;
        o.x = ce.x - s * acc.x;
        o.y = ce.y - s * acc.y;
        o.z = ce.z - s * acc.z;
        o.w = ce.w - s * acc.w;
        reinterpret_cast<float4*>(out_centers + (size_t)c0 * FEAT_DIM)[t] = o;
    }
}

// ---------------------------------------------------------------------------
extern "C" void kernel_launch(void* const* d_in, const int* in_sizes, int n_in,
                              void* d_out, int out_size) {
    const float* features = (const float*)d_in[0];
    const float* centers  = (const float*)d_in[1];
    const int*   labels   = (const int*)d_in[2];

    float* out_result      = (float*)d_out;          // [BATCH]
    float* out_new_centers = (float*)d_out + BATCH;  // [NUM_CLASSES * FEAT_DIM]

    center_loss_fused_kernel<<<NUM_CLASSES / G, THREADS>>>(
        features, centers, labels, out_result, out_new_centers);
}